// round 17
// baseline (speedup 1.0000x reference)
#include <cuda_runtime.h>
#include <cuda_bf16.h>

#define MAXN 100000
#define MAXE 1600000
#define DD   64
#define ALLOC_T 1024
#define GRP 8

// Scratch (device globals — allocations forbidden).
__device__ int   g_cnt[MAXN];                  // in-degree (excl. self loop)
__device__ int   g_cur[MAXN];                  // bucket cursor
__device__ float g_dinv[MAXN];                 // (deg incl self)^-1/2
__device__ int   g_total;                      // bucket allocator
__device__ unsigned long long g_rec[MAXE];     // src | dst<<32, dst-bucketed
__device__ float g_agg[(size_t)MAXN * DD];     // aggregated rows (25.6 MB)

// K1: zero histogram + allocator
__global__ void k_init(int n) {
    int i = blockIdx.x * blockDim.x + threadIdx.x;
    if (i < n) g_cnt[i] = 0;
    if (i == 0) g_total = 0;
}

// K2: int histogram of dst — 4 edges/thread, int4 load, 4 independent atomics
__global__ void k_count4(const int* __restrict__ ei, int E) {
    int t = blockIdx.x * blockDim.x + threadIdx.x;
    int base = t * 4;
    if (base + 4 <= E) {
        int4 d = *reinterpret_cast<const int4*>(&ei[E + base]);
        atomicAdd(&g_cnt[d.x], 1);
        atomicAdd(&g_cnt[d.y], 1);
        atomicAdd(&g_cnt[d.z], 1);
        atomicAdd(&g_cnt[d.w], 1);
    } else {
        for (int e = base; e < E; e++) atomicAdd(&g_cnt[ei[E + e]], 1);
    }
}

// K3: scan-free bucket allocation (block scan + one global atomic per block);
// also dinv = rsqrt(cnt+1).
__global__ void __launch_bounds__(ALLOC_T) k_alloc(int n) {
    int i = blockIdx.x * ALLOC_T + threadIdx.x;
    int lane = threadIdx.x & 31;
    int wid  = threadIdx.x >> 5;
    int c = (i < n) ? g_cnt[i] : 0;

    int s = c;
#pragma unroll
    for (int d = 1; d < 32; d <<= 1) {
        int v = __shfl_up_sync(0xffffffffu, s, d);
        if (lane >= d) s += v;
    }

    __shared__ int wsum[32];
    __shared__ int blockbase;
    if (lane == 31) wsum[wid] = s;
    __syncthreads();
    if (wid == 0) {
        int ws = (lane < (ALLOC_T / 32)) ? wsum[lane] : 0;
#pragma unroll
        for (int d = 1; d < 32; d <<= 1) {
            int v = __shfl_up_sync(0xffffffffu, ws, d);
            if (lane >= d) ws += v;
        }
        wsum[lane] = ws;
        if (lane == 31) blockbase = atomicAdd(&g_total, ws);
    }
    __syncthreads();
    if (i < n) {
        int prev = (wid > 0) ? wsum[wid - 1] : 0;
        g_cur[i]  = blockbase + prev + (s - c);
        g_dinv[i] = rsqrtf((float)(c + 1));
    }
}

// K4: fill dst-buckets — 4 edges/thread, int4 loads, 4 independent
// atomic->store chains (MLP=4 against ATOMG latency).
__global__ void k_fill4(const int* __restrict__ ei, int E) {
    int t = blockIdx.x * blockDim.x + threadIdx.x;
    int base = t * 4;
    if (base + 4 <= E) {
        int4 s = *reinterpret_cast<const int4*>(&ei[base]);
        int4 d = *reinterpret_cast<const int4*>(&ei[E + base]);
        int p0 = atomicAdd(&g_cur[d.x], 1);
        int p1 = atomicAdd(&g_cur[d.y], 1);
        int p2 = atomicAdd(&g_cur[d.z], 1);
        int p3 = atomicAdd(&g_cur[d.w], 1);
        g_rec[p0] = (unsigned)s.x | ((unsigned long long)(unsigned)d.x << 32);
        g_rec[p1] = (unsigned)s.y | ((unsigned long long)(unsigned)d.y << 32);
        g_rec[p2] = (unsigned)s.z | ((unsigned long long)(unsigned)d.z << 32);
        g_rec[p3] = (unsigned)s.w | ((unsigned long long)(unsigned)d.w << 32);
    } else {
        for (int e = base; e < E; e++) {
            int s = ei[e];
            int d = ei[E + e];
            int pos = atomicAdd(&g_cur[d], 1);
            g_rec[pos] = (unsigned)s | ((unsigned long long)(unsigned)d << 32);
        }
    }
}

// K5: agg[i,:] = x[i,:] * dinv[i]^2 (self loop; resets agg every replay)
__global__ void k_selfinit(const float4* __restrict__ x4, int n) {
    int idx = blockIdx.x * blockDim.x + threadIdx.x;
    if (idx >= n * (DD / 4)) return;
    int i = idx >> 4;
    float d = g_dinv[i];
    float s = d * d;
    float4 v = x4[idx];
    v.x *= s; v.y *= s; v.z *= s; v.w *= s;
    reinterpret_cast<float4*>(g_agg)[idx] = v;
}

__device__ __forceinline__ void red_v4(float* dst, float4 a) {
    asm volatile("red.global.add.v4.f32 [%0], {%1, %2, %3, %4};"
                 :: "l"(dst), "f"(a.x), "f"(a.y), "f"(a.z), "f"(a.w)
                 : "memory");
}
__device__ __forceinline__ void facc(float4& a, float4 v, float w) {
    a.x += w * v.x; a.y += w * v.y; a.z += w * v.z; a.w += w * v.w;
}
__device__ __forceinline__ float4 fmul(float4 v, float w) {
    return make_float4(w * v.x, w * v.y, w * v.z, w * v.w);
}

// K6: merged scatter, GRP=8 bucket slots x 16 feature chunks per thread.
// Bit-reversed group order de-clusters same-address atomics in time.
__global__ void __launch_bounds__(256) k_scatter8(
    const float4* __restrict__ x4, int E, int kbits, int ngroups)
{
    int gid  = blockIdx.x * blockDim.x + threadIdx.x;
    int glin = gid >> 4;
    int c    = gid & 15;
    int gp   = (int)(__brev((unsigned)glin) >> (32 - kbits));
    if (gp >= ngroups) return;
    int base = gp * GRP;

    if (base + GRP <= E) {
        unsigned long long r[GRP];
#pragma unroll
        for (int i = 0; i < GRP; i++) r[i] = __ldg(&g_rec[base + i]);
        int s[GRP], d[GRP];
#pragma unroll
        for (int i = 0; i < GRP; i++) {
            s[i] = (int)(unsigned)r[i];
            d[i] = (int)(unsigned)(r[i] >> 32);
        }
        float4 v[GRP];
#pragma unroll
        for (int i = 0; i < GRP; i++) v[i] = __ldg(&x4[(size_t)s[i] * 16 + c]);
        float w[GRP];
#pragma unroll
        for (int i = 0; i < GRP; i++)
            w[i] = __ldg(&g_dinv[s[i]]) * __ldg(&g_dinv[d[i]]);

        float4 acc = fmul(v[0], w[0]);
        int cur = d[0];
#pragma unroll
        for (int i = 1; i < GRP; i++) {
            if (d[i] == cur) facc(acc, v[i], w[i]);
            else {
                red_v4(&g_agg[(size_t)cur * DD + c * 4], acc);
                acc = fmul(v[i], w[i]);
                cur = d[i];
            }
        }
        red_v4(&g_agg[(size_t)cur * DD + c * 4], acc);
    } else {
        int m = E - base;
        unsigned long long r0 = __ldg(&g_rec[base]);
        int s0 = (int)(unsigned)r0;
        int cur = (int)(unsigned)(r0 >> 32);
        float w0 = __ldg(&g_dinv[s0]) * __ldg(&g_dinv[cur]);
        float4 acc = fmul(__ldg(&x4[(size_t)s0 * 16 + c]), w0);
        for (int j = 1; j < m; j++) {
            unsigned long long rj = __ldg(&g_rec[base + j]);
            int sj = (int)(unsigned)rj;
            int dj = (int)(unsigned)(rj >> 32);
            float wj = __ldg(&g_dinv[sj]) * __ldg(&g_dinv[dj]);
            float4 vj = __ldg(&x4[(size_t)sj * 16 + c]);
            if (dj == cur) facc(acc, vj, wj);
            else {
                red_v4(&g_agg[(size_t)cur * DD + c * 4], acc);
                acc = fmul(vj, wj);
                cur = dj;
            }
        }
        red_v4(&g_agg[(size_t)cur * DD + c * 4], acc);
    }
}

// ---------------------------------------------------------------------------
// Packed f32x2 helpers (B300 FFMA2 via PTX)
__device__ __forceinline__ unsigned long long pk2(float lo, float hi) {
    unsigned long long r;
    asm("mov.b64 %0, {%1, %2};" : "=l"(r) : "f"(lo), "f"(hi));
    return r;
}
__device__ __forceinline__ float2 upk2(unsigned long long v) {
    float2 t;
    asm("mov.b64 {%0, %1}, %2;" : "=f"(t.x), "=f"(t.y) : "l"(v));
    return t;
}
__device__ __forceinline__ unsigned long long fma2(
    unsigned long long a, unsigned long long b, unsigned long long c) {
    unsigned long long r;
    asm("fma.rn.f32x2 %0, %1, %2, %3;" : "=l"(r) : "l"(a), "l"(b), "l"(c));
    return r;
}

// K7: out = agg @ W^T + b (one node per thread, FFMA2 core)
__global__ void k_gemm(const float* __restrict__ W,
                       const float* __restrict__ b,
                       float* __restrict__ out, int n) {
    __shared__ float sWT[DD * DD];   // sWT[k*64 + j] = W[j*64 + k]
    for (int idx = threadIdx.x; idx < DD * DD; idx += blockDim.x) {
        int j = idx >> 6, k = idx & 63;
        sWT[k * DD + j] = W[idx];
    }
    __syncthreads();

    int node = blockIdx.x * blockDim.x + threadIdx.x;
    if (node >= n) return;

    unsigned long long acc2[32];
    const unsigned long long* b2 = reinterpret_cast<const unsigned long long*>(b);
#pragma unroll
    for (int m = 0; m < 32; m++) acc2[m] = __ldg(&b2[m]);

    const float4* a4 = reinterpret_cast<const float4*>(g_agg) + (size_t)node * 16;
#pragma unroll
    for (int kk = 0; kk < 16; kk++) {
        float4 av = a4[kk];
#pragma unroll
        for (int s = 0; s < 4; s++) {
            float a = (s == 0) ? av.x : (s == 1) ? av.y : (s == 2) ? av.z : av.w;
            unsigned long long a2 = pk2(a, a);
            const unsigned long long* wr = reinterpret_cast<const unsigned long long*>(
                &sWT[(kk * 4 + s) * DD]);
#pragma unroll
            for (int m = 0; m < 32; m++)
                acc2[m] = fma2(a2, wr[m], acc2[m]);
        }
    }

    float4* o4 = reinterpret_cast<float4*>(out) + (size_t)node * 16;
#pragma unroll
    for (int m = 0; m < 16; m++) {
        float2 lo = upk2(acc2[2 * m]);
        float2 hi = upk2(acc2[2 * m + 1]);
        o4[m] = make_float4(lo.x, lo.y, hi.x, hi.y);
    }
}

// ---------------------------------------------------------------------------
extern "C" void kernel_launch(void* const* d_in, const int* in_sizes, int n_in,
                              void* d_out, int out_size) {
    const float* x  = (const float*)d_in[0];
    const int*   ei = (const int*)d_in[1];
    const float* W  = (const float*)d_in[2];
    const float* b  = (const float*)d_in[3];
    float* out = (float*)d_out;

    int D = in_sizes[3];          // 64
    int n = in_sizes[0] / D;      // 100000
    int E = in_sizes[1] / 2;      // 1600000

    const int T = 256;
    k_init <<<(n + T - 1) / T, T>>>(n);

    int qthreads = (E + 3) / 4;
    k_count4<<<(qthreads + T - 1) / T, T>>>(ei, E);
    k_alloc <<<(n + ALLOC_T - 1) / ALLOC_T, ALLOC_T>>>(n);
    k_fill4 <<<(qthreads + T - 1) / T, T>>>(ei, E);

    int self_work = n * (D / 4);
    k_selfinit<<<(self_work + T - 1) / T, T>>>((const float4*)x, n);

    int ngroups = (E + GRP - 1) / GRP;
    int kbits = 0;
    while ((1 << kbits) < ngroups) kbits++;
    long long sc = (long long)(1 << kbits) * 16;
    int sc_blocks = (int)((sc + T - 1) / T);
    k_scatter8<<<sc_blocks, T>>>((const float4*)x, E, kbits, ngroups);

    k_gemm<<<(n + T - 1) / T, T>>>(W, b, out, n);
}